// round 1
// baseline (speedup 1.0000x reference)
#include <cuda_runtime.h>

#define N_NODES 50000
#define N_EDGES 1600000
#define BATCH   4
#define T_STEPS 50
#define DT      0.02f

// ---- scratch (static device globals; no allocation allowed) ----
__device__ int    g_deg[N_NODES];
__device__ int    g_row_start[N_NODES + 1];
__device__ int    g_cursor[N_NODES];
__device__ int    g_src_perm[N_EDGES];
__device__ float  g_w_perm[N_EDGES];
__device__ float4 g_v[N_NODES];
__device__ float4 g_rates[2][N_NODES];
__device__ float  g_alpha[N_NODES];

// ---------------------------------------------------------------------------
// Setup kernels (run every launch; graph-capturable, deterministic workload)
// ---------------------------------------------------------------------------

__global__ void init_kernel(const float* __restrict__ bias,
                            const float* __restrict__ tc) {
    int n = blockIdx.x * blockDim.x + threadIdx.x;
    if (n >= N_NODES) return;
    g_deg[n] = 0;
    float b   = bias[n];
    float tau = fmaxf(tc[n], DT);
    g_alpha[n] = DT / tau;
    g_v[n] = make_float4(b, b, b, b);
    float r = fmaxf(b, 0.0f);
    g_rates[0][n] = make_float4(r, r, r, r);
}

__global__ void hist_kernel(const int* __restrict__ tgt) {
    int e = blockIdx.x * blockDim.x + threadIdx.x;
    if (e < N_EDGES) atomicAdd(&g_deg[tgt[e]], 1);
}

// single-block tiled exclusive scan over 50K degrees (shfl-based, ~5us)
__global__ void scan_kernel() {
    __shared__ int warp_sums[32];
    __shared__ int s_carry;
    int lane = threadIdx.x & 31;
    int wid  = threadIdx.x >> 5;
    if (threadIdx.x == 0) s_carry = 0;
    __syncthreads();
    for (int base = 0; base < N_NODES; base += 1024) {
        int i   = base + threadIdx.x;
        int val = (i < N_NODES) ? g_deg[i] : 0;
        int inc = val;
        #pragma unroll
        for (int d = 1; d < 32; d <<= 1) {
            int y = __shfl_up_sync(0xffffffffu, inc, d);
            if (lane >= d) inc += y;
        }
        if (lane == 31) warp_sums[wid] = inc;
        __syncthreads();
        if (wid == 0) {
            int w = warp_sums[lane];
            #pragma unroll
            for (int d = 1; d < 32; d <<= 1) {
                int y = __shfl_up_sync(0xffffffffu, w, d);
                if (lane >= d) w += y;
            }
            warp_sums[lane] = w;
        }
        __syncthreads();
        int excl = s_carry + (inc - val) + (wid > 0 ? warp_sums[wid - 1] : 0);
        if (i < N_NODES) { g_row_start[i] = excl; g_cursor[i] = excl; }
        int tile_total = warp_sums[31];
        __syncthreads();                 // everyone has consumed s_carry
        if (threadIdx.x == 0) s_carry += tile_total;
        __syncthreads();                 // s_carry updated before next tile
    }
    if (threadIdx.x == 0) g_row_start[N_NODES] = s_carry;
}

__global__ void build_kernel(const int*   __restrict__ src,
                             const int*   __restrict__ tgt,
                             const float* __restrict__ sign,
                             const float* __restrict__ cnt,
                             const float* __restrict__ strg) {
    int e = blockIdx.x * blockDim.x + threadIdx.x;
    if (e >= N_EDGES) return;
    float w = sign[e] * fmaxf(cnt[e], 0.0f) * fmaxf(strg[e], 0.0f);
    int t   = tgt[e];
    int pos = atomicAdd(&g_cursor[t], 1);
    g_src_perm[pos] = src[e];
    g_w_perm[pos]   = w;
}

// ---------------------------------------------------------------------------
// Main step: one thread owns one target node; fuse gather+reduce+Euler+output.
// No atomics. rates double-buffered (parity) across launches.
// ---------------------------------------------------------------------------

__global__ __launch_bounds__(256)
void step_kernel(const float* __restrict__ x,
                 const float* __restrict__ bias,
                 float* __restrict__ out,
                 int t, int parity) {
    int n = blockIdx.x * blockDim.x + threadIdx.x;
    if (n >= N_NODES) return;

    const float4* __restrict__ rr = g_rates[parity];
    int beg = g_row_start[n];
    int end = g_row_start[n + 1];

    float ax = 0.f, ay = 0.f, az = 0.f, aw = 0.f;
    int e = beg;
    // 4-wide manual unroll: 4 independent gathers in flight per thread
    for (; e + 4 <= end; e += 4) {
        int   s0 = g_src_perm[e + 0], s1 = g_src_perm[e + 1];
        int   s2 = g_src_perm[e + 2], s3 = g_src_perm[e + 3];
        float w0 = g_w_perm[e + 0],   w1 = g_w_perm[e + 1];
        float w2 = g_w_perm[e + 2],   w3 = g_w_perm[e + 3];
        float4 r0 = __ldg(&rr[s0]);
        float4 r1 = __ldg(&rr[s1]);
        float4 r2 = __ldg(&rr[s2]);
        float4 r3 = __ldg(&rr[s3]);
        ax += r0.x * w0 + r1.x * w1 + r2.x * w2 + r3.x * w3;
        ay += r0.y * w0 + r1.y * w1 + r2.y * w2 + r3.y * w3;
        az += r0.z * w0 + r1.z * w1 + r2.z * w2 + r3.z * w3;
        aw += r0.w * w0 + r1.w * w1 + r2.w * w2 + r3.w * w3;
    }
    for (; e < end; e++) {
        int   s = g_src_perm[e];
        float w = g_w_perm[e];
        float4 r = __ldg(&rr[s]);
        ax += r.x * w; ay += r.y * w; az += r.z * w; aw += r.w * w;
    }

    float4 v = g_v[n];
    float  b = bias[n];
    float  a = g_alpha[n];
    const int TN = T_STEPS * N_NODES;
    int o = t * N_NODES + n;
    float x0 = x[0 * TN + o];
    float x1 = x[1 * TN + o];
    float x2 = x[2 * TN + o];
    float x3 = x[3 * TN + o];

    v.x += a * (b - v.x + ax + x0);
    v.y += a * (b - v.y + ay + x1);
    v.z += a * (b - v.z + az + x2);
    v.w += a * (b - v.w + aw + x3);
    g_v[n] = v;

    float4 r = make_float4(fmaxf(v.x, 0.f), fmaxf(v.y, 0.f),
                           fmaxf(v.z, 0.f), fmaxf(v.w, 0.f));
    g_rates[parity ^ 1][n] = r;

    out[0 * TN + o] = r.x;
    out[1 * TN + o] = r.y;
    out[2 * TN + o] = r.z;
    out[3 * TN + o] = r.w;
}

// ---------------------------------------------------------------------------

extern "C" void kernel_launch(void* const* d_in, const int* in_sizes, int n_in,
                              void* d_out, int out_size) {
    const float* x    = (const float*)d_in[0];
    const float* bias = (const float*)d_in[1];
    const float* tc   = (const float*)d_in[2];
    const float* sign = (const float*)d_in[3];
    const float* cnt  = (const float*)d_in[4];
    const float* strg = (const float*)d_in[5];
    const int*   src  = (const int*)d_in[6];
    const int*   tgt  = (const int*)d_in[7];
    float*       out  = (float*)d_out;

    int nb = (N_NODES + 255) / 256;
    int eb = (N_EDGES + 255) / 256;

    init_kernel<<<nb, 256>>>(bias, tc);
    hist_kernel<<<eb, 256>>>(tgt);
    scan_kernel<<<1, 1024>>>();
    build_kernel<<<eb, 256>>>(src, tgt, sign, cnt, strg);

    for (int t = 0; t < T_STEPS; t++)
        step_kernel<<<nb, 256>>>(x, bias, out, t, t & 1);
}

// round 2
// speedup vs baseline: 1.6254x; 1.6254x over previous
#include <cuda_runtime.h>
#include <cuda_fp16.h>

#define N_NODES 50000
#define N_EDGES 1600000
#define BATCH   4
#define T_STEPS 50
#define DT      0.02f
// padded edge capacity: each node padded to multiple of 4 edges
#define EDGE_MAX (N_EDGES + 3 * N_NODES)

// ---- scratch (static device globals; no allocation allowed) ----
__device__ int      g_deg[N_NODES];
__device__ int      g_row_start[N_NODES + 1];
__device__ int      g_cursor[N_NODES];
__device__ unsigned g_edges[EDGE_MAX];          // (src<<16) | fp16(weight)
__device__ float    g_vp[BATCH][N_NODES];       // planar membrane state
__device__ float4   g_rates[2][N_NODES];        // double-buffered relu(v), batch-vec
__device__ float    g_alpha[N_NODES];

// ---------------------------------------------------------------------------
// Setup kernels
// ---------------------------------------------------------------------------

// covers max(N_NODES, EDGE_MAX) range: zero edges + init node state
__global__ void init_kernel(const float* __restrict__ bias,
                            const float* __restrict__ tc) {
    int i = blockIdx.x * blockDim.x + threadIdx.x;
    if (i < EDGE_MAX) g_edges[i] = 0u;          // dummy edge: src=0, w=+0.0h
    if (i >= N_NODES) return;
    g_deg[i] = 0;
    float b   = bias[i];
    float tau = fmaxf(tc[i], DT);
    g_alpha[i] = DT / tau;
    float r = fmaxf(b, 0.0f);
    #pragma unroll
    for (int q = 0; q < BATCH; q++) g_vp[q][i] = b;
    g_rates[0][i] = make_float4(r, r, r, r);
}

__global__ void hist_kernel(const int* __restrict__ tgt) {
    int e = blockIdx.x * blockDim.x + threadIdx.x;
    if (e < N_EDGES) atomicAdd(&g_deg[tgt[e]], 1);
}

// single-block tiled exclusive scan over padded degrees
__global__ void scan_kernel() {
    __shared__ int warp_sums[32];
    __shared__ int s_carry;
    int lane = threadIdx.x & 31;
    int wid  = threadIdx.x >> 5;
    if (threadIdx.x == 0) s_carry = 0;
    __syncthreads();
    for (int base = 0; base < N_NODES; base += 1024) {
        int i   = base + threadIdx.x;
        int val = (i < N_NODES) ? ((g_deg[i] + 3) & ~3) : 0;  // pad to mult of 4
        int inc = val;
        #pragma unroll
        for (int d = 1; d < 32; d <<= 1) {
            int y = __shfl_up_sync(0xffffffffu, inc, d);
            if (lane >= d) inc += y;
        }
        if (lane == 31) warp_sums[wid] = inc;
        __syncthreads();
        if (wid == 0) {
            int w = warp_sums[lane];
            #pragma unroll
            for (int d = 1; d < 32; d <<= 1) {
                int y = __shfl_up_sync(0xffffffffu, w, d);
                if (lane >= d) w += y;
            }
            warp_sums[lane] = w;
        }
        __syncthreads();
        int excl = s_carry + (inc - val) + (wid > 0 ? warp_sums[wid - 1] : 0);
        if (i < N_NODES) { g_row_start[i] = excl; g_cursor[i] = excl; }
        int tile_total = warp_sums[31];
        __syncthreads();
        if (threadIdx.x == 0) s_carry += tile_total;
        __syncthreads();
    }
    if (threadIdx.x == 0) g_row_start[N_NODES] = s_carry;
}

__global__ void build_kernel(const int*   __restrict__ src,
                             const int*   __restrict__ tgt,
                             const float* __restrict__ sign,
                             const float* __restrict__ cnt,
                             const float* __restrict__ strg) {
    int e = blockIdx.x * blockDim.x + threadIdx.x;
    if (e >= N_EDGES) return;
    float w = sign[e] * fmaxf(cnt[e], 0.0f) * fmaxf(strg[e], 0.0f);
    unsigned hw = (unsigned)__half_as_ushort(__float2half_rn(w));
    unsigned packed = ((unsigned)src[e] << 16) | hw;
    int pos = atomicAdd(&g_cursor[tgt[e]], 1);
    g_edges[pos] = packed;
}

// ---------------------------------------------------------------------------
// Step: 4 threads (one quad) per target node. Each thread takes every 4th
// 4-edge chunk (one LDG.128 of packed edges + 4 float4 gathers), then quad
// shfl_xor reduction; each lane then owns one batch element's Euler update.
// ---------------------------------------------------------------------------

__global__ __launch_bounds__(256)
void step_kernel(const float* __restrict__ x,
                 const float* __restrict__ bias,
                 float* __restrict__ out,
                 int t, int parity) {
    int gtid = blockIdx.x * blockDim.x + threadIdx.x;
    int n    = gtid >> 2;                  // node (uniform across quad)
    if (n >= N_NODES) return;
    int lane  = threadIdx.x & 31;
    int q     = lane & 3;                  // quad lane == batch element
    unsigned qmask = 0xFu << (lane & ~3);

    const float4* __restrict__ rr = g_rates[parity];
    int beg = g_row_start[n];
    int end = g_row_start[n + 1];
    int nch = (end - beg) >> 2;            // 4-edge chunks (padded)

    float ax = 0.f, ay = 0.f, az = 0.f, aw = 0.f;
    const uint4* ep = reinterpret_cast<const uint4*>(&g_edges[beg]);
    for (int c = q; c < nch; c += 4) {
        uint4 e4 = ep[c];
        int s0 = e4.x >> 16, s1 = e4.y >> 16, s2 = e4.z >> 16, s3 = e4.w >> 16;
        float w0 = __half2float(__ushort_as_half((unsigned short)(e4.x & 0xFFFFu)));
        float w1 = __half2float(__ushort_as_half((unsigned short)(e4.y & 0xFFFFu)));
        float w2 = __half2float(__ushort_as_half((unsigned short)(e4.z & 0xFFFFu)));
        float w3 = __half2float(__ushort_as_half((unsigned short)(e4.w & 0xFFFFu)));
        float4 r0 = __ldg(&rr[s0]);
        float4 r1 = __ldg(&rr[s1]);
        float4 r2 = __ldg(&rr[s2]);
        float4 r3 = __ldg(&rr[s3]);
        ax += r0.x * w0 + r1.x * w1 + r2.x * w2 + r3.x * w3;
        ay += r0.y * w0 + r1.y * w1 + r2.y * w2 + r3.y * w3;
        az += r0.z * w0 + r1.z * w1 + r2.z * w2 + r3.z * w3;
        aw += r0.w * w0 + r1.w * w1 + r2.w * w2 + r3.w * w3;
    }

    // quad reduction: afterwards every lane holds the full sums
    #pragma unroll
    for (int off = 1; off <= 2; off <<= 1) {
        ax += __shfl_xor_sync(qmask, ax, off);
        ay += __shfl_xor_sync(qmask, ay, off);
        az += __shfl_xor_sync(qmask, az, off);
        aw += __shfl_xor_sync(qmask, aw, off);
    }
    float sum = (q == 0) ? ax : (q == 1) ? ay : (q == 2) ? az : aw;

    const int TN = T_STEPS * N_NODES;
    int   o  = t * N_NODES + n;
    float b  = bias[n];
    float a  = g_alpha[n];
    float v  = g_vp[q][n];
    float xv = __ldcs(&x[q * TN + o]);     // streaming: don't pollute L2

    v += a * (b - v + sum + xv);
    g_vp[q][n] = v;

    float r = fmaxf(v, 0.f);
    reinterpret_cast<float*>(&g_rates[parity ^ 1][n])[q] = r;
    __stcs(&out[q * TN + o], r);           // streaming store
}

// ---------------------------------------------------------------------------

extern "C" void kernel_launch(void* const* d_in, const int* in_sizes, int n_in,
                              void* d_out, int out_size) {
    const float* x    = (const float*)d_in[0];
    const float* bias = (const float*)d_in[1];
    const float* tc   = (const float*)d_in[2];
    const float* sign = (const float*)d_in[3];
    const float* cnt  = (const float*)d_in[4];
    const float* strg = (const float*)d_in[5];
    const int*   src  = (const int*)d_in[6];
    const int*   tgt  = (const int*)d_in[7];
    float*       out  = (float*)d_out;

    int ib = (EDGE_MAX + 255) / 256;            // covers edges + nodes
    int eb = (N_EDGES + 255) / 256;
    int sb = (N_NODES * 4 + 255) / 256;         // 4 threads per node

    init_kernel<<<ib, 256>>>(bias, tc);
    hist_kernel<<<eb, 256>>>(tgt);
    scan_kernel<<<1, 1024>>>();
    build_kernel<<<eb, 256>>>(src, tgt, sign, cnt, strg);

    for (int t = 0; t < T_STEPS; t++)
        step_kernel<<<sb, 256>>>(x, bias, out, t, t & 1);
}